// round 11
// baseline (speedup 1.0000x reference)
#include <cuda_runtime.h>
#include <cuda_bf16.h>
#include <cstdint>

#define NN 50000
#define EE 800000
#define SS 2
#define DIN 128
#define DNOISE 64
#define DH 192          // DIN + DNOISE
#define DOUT 256
#define SN (SS * NN)    // 100000 rows

// ---------------- scratch (static device globals; no allocation) ----------------
__device__ float          g_h1[(size_t)SN * DOUT];        // gemmE output (fp32)
__device__ float          g_yX[(size_t)NN * DOUT];        // zX @ W0X (sample-invariant)
__device__ unsigned short g_A0h[(size_t)SN * DH];         // layer-0 A, bf16 hi plane
__device__ unsigned short g_A0l[(size_t)SN * DH];
__device__ unsigned short g_A1h[(size_t)SN * DOUT];
__device__ unsigned short g_A1l[(size_t)SN * DOUT];
__device__ unsigned short g_W0h[DOUT * DH];               // W0^T split planes [n][k]
__device__ unsigned short g_W0l[DOUT * DH];
__device__ unsigned short g_W1h[DOUT * DOUT];
__device__ unsigned short g_W1l[DOUT * DOUT];
__device__ int g_counts[NN];
__device__ int g_rowptr[NN + 1];
__device__ int g_cursor[NN];
__device__ int g_csr[EE];

// ---------------- small helpers ----------------
__device__ __forceinline__ float4 f4_zero() { return make_float4(0.f, 0.f, 0.f, 0.f); }
__device__ __forceinline__ void f4_add(float4& a, const float4 b) {
    a.x += b.x; a.y += b.y; a.z += b.z; a.w += b.w;
}

__device__ __forceinline__ void mma_bf16(float* c, const uint32_t* a, const uint32_t* b) {
    asm volatile(
        "mma.sync.aligned.m16n8k16.row.col.f32.bf16.bf16.f32 "
        "{%0,%1,%2,%3},{%4,%5,%6,%7},{%8,%9},{%0,%1,%2,%3};\n"
        : "+f"(c[0]), "+f"(c[1]), "+f"(c[2]), "+f"(c[3])
        : "r"(a[0]), "r"(a[1]), "r"(a[2]), "r"(a[3]), "r"(b[0]), "r"(b[1]));
}

__device__ __forceinline__ void ldsm_x4(uint32_t& r0, uint32_t& r1, uint32_t& r2, uint32_t& r3,
                                        uint32_t addr) {
    asm volatile("ldmatrix.sync.aligned.m8n8.x4.shared.b16 {%0,%1,%2,%3},[%4];"
                 : "=r"(r0), "=r"(r1), "=r"(r2), "=r"(r3) : "r"(addr));
}

__device__ __forceinline__ void cp16(uint32_t smem_dst, const void* gsrc) {
    asm volatile("cp.async.ca.shared.global [%0], [%1], 16;\n" :: "r"(smem_dst), "l"(gsrc));
}
__device__ __forceinline__ void cp_commit() { asm volatile("cp.async.commit_group;\n"); }
template <int N>
__device__ __forceinline__ void cp_wait() { asm volatile("cp.async.wait_group %0;\n" :: "n"(N)); }

// split one float into bf16 hi + bf16 lo (bits)
__device__ __forceinline__ void splitf(float x, unsigned short& h, unsigned short& l) {
    __nv_bfloat16 hb = __float2bfloat16(x);
    __nv_bfloat16 lb = __float2bfloat16(x - __bfloat162float(hb));
    h = __bfloat16_as_ushort(hb);
    l = __bfloat16_as_ushort(lb);
}
__device__ __forceinline__ void split4(float4 v, uint2& hi, uint2& lo) {
    unsigned short hx, lx, hy, ly, hz, lz, hw, lw;
    splitf(v.x, hx, lx); splitf(v.y, hy, ly);
    splitf(v.z, hz, lz); splitf(v.w, hw, lw);
    hi.x = (uint32_t)hx | ((uint32_t)hy << 16);
    hi.y = (uint32_t)hz | ((uint32_t)hw << 16);
    lo.x = (uint32_t)lx | ((uint32_t)ly << 16);
    lo.y = (uint32_t)lz | ((uint32_t)lw << 16);
}

// ---------------- CSR build ----------------
__global__ void k_count(const int* __restrict__ dst) {
    int e = blockIdx.x * blockDim.x + threadIdx.x;
    if (e < EE) atomicAdd(&g_counts[dst[e]], 1);
}

__global__ void k_scan() {
    const int CH = (NN + 1023) / 1024;   // 49
    __shared__ int wsum[32];
    int t = threadIdx.x, lane = t & 31, w = t >> 5;
    int base = t * CH;
    int sum = 0;
    for (int i = 0; i < CH; i++) {
        int n = base + i;
        if (n < NN) sum += g_counts[n];
    }
    int incl = sum;
    #pragma unroll
    for (int d = 1; d < 32; d <<= 1) {
        int y = __shfl_up_sync(0xffffffffu, incl, d);
        if (lane >= d) incl += y;
    }
    if (lane == 31) wsum[w] = incl;
    __syncthreads();
    if (w == 0) {
        int v = wsum[lane];
        #pragma unroll
        for (int d = 1; d < 32; d <<= 1) {
            int y = __shfl_up_sync(0xffffffffu, v, d);
            if (lane >= d) v += y;
        }
        wsum[lane] = v;
    }
    __syncthreads();
    int offset = incl - sum + (w > 0 ? wsum[w - 1] : 0);
    int run = offset;
    for (int i = 0; i < CH; i++) {
        int n = base + i;
        if (n < NN) {
            g_rowptr[n] = run;
            g_cursor[n] = run;
            run += g_counts[n];
        }
    }
    if (t == 1023) g_rowptr[NN] = wsum[31];
}

__global__ void k_scatter(const int* __restrict__ src, const int* __restrict__ dst) {
    int e = blockIdx.x * blockDim.x + threadIdx.x;
    if (e < EE) {
        int p = atomicAdd(&g_cursor[dst[e]], 1);
        g_csr[p] = src[e];
    }
}

// ---------------- weight pre-split: W[K][256] fp32 -> Wt planes [256][K] bf16 ----------------
template <int K>
__global__ void k_split_w(const float* __restrict__ W,
                          unsigned short* __restrict__ Wh, unsigned short* __restrict__ Wl) {
    int id = blockIdx.x * blockDim.x + threadIdx.x;
    if (id >= 256 * K) return;
    int n = id % 256, k = id / 256;
    unsigned short h, l;
    splitf(W[(size_t)k * 256 + n], h, l);
    Wh[(size_t)n * K + k] = h;
    Wl[(size_t)n * K + k] = l;
}

// ---------------- layer-0 aggregation (fused concat + eps passthrough) ----------------
// TWO warps per node: role 0 = X part; role 1 = eps parts (both samples) + out2 store.
__global__ void k_agg0(const float* __restrict__ X, const float* __restrict__ eps,
                       unsigned short* __restrict__ Zh, unsigned short* __restrict__ Zl,
                       const float* __restrict__ epsv, float* __restrict__ out2) {
    unsigned gw = (blockIdx.x * blockDim.x + threadIdx.x) >> 5;
    unsigned lane = threadIdx.x & 31;
    unsigned n = gw >> 1;
    unsigned role = gw & 1;
    if (n >= NN) return;
    float sc = 1.0f + *epsv;
    int beg = g_rowptr[n], end = g_rowptr[n + 1];

    if (role == 0) {
        const float4* X4 = (const float4*)X;     // [NN][32]
        float4 a = f4_zero();
        int e = beg;
        for (; e + 4 <= end; e += 4) {
            unsigned i0 = g_csr[e + 0], i1 = g_csr[e + 1];
            unsigned i2 = g_csr[e + 2], i3 = g_csr[e + 3];
            float4 x0 = X4[i0 * 32u + lane];
            float4 x1 = X4[i1 * 32u + lane];
            float4 x2 = X4[i2 * 32u + lane];
            float4 x3 = X4[i3 * 32u + lane];
            f4_add(a, x0); f4_add(a, x1); f4_add(a, x2); f4_add(a, x3);
        }
        for (; e < end; e++) {
            unsigned src = g_csr[e];
            f4_add(a, X4[src * 32u + lane]);
        }
        float4 s = X4[n * 32u + lane];
        float4 o;
        o.x = fmaf(sc, s.x, a.x); o.y = fmaf(sc, s.y, a.y);
        o.z = fmaf(sc, s.z, a.z); o.w = fmaf(sc, s.w, a.w);
        uint2 hi, lo;
        split4(o, hi, lo);
        *(uint2*)&Zh[(size_t)n * DH + lane * 4] = hi;
        *(uint2*)&Zl[(size_t)n * DH + lane * 4] = lo;
    } else {
        const float4* E4 = (const float4*)eps;   // [2*NN][16]
        unsigned sb = (lane >> 4) * NN;          // sample base
        unsigned el = lane & 15;
        float4 a = f4_zero();
        int e = beg;
        for (; e + 4 <= end; e += 4) {
            unsigned i0 = g_csr[e + 0], i1 = g_csr[e + 1];
            unsigned i2 = g_csr[e + 2], i3 = g_csr[e + 3];
            float4 x0 = E4[(sb + i0) * 16u + el];
            float4 x1 = E4[(sb + i1) * 16u + el];
            float4 x2 = E4[(sb + i2) * 16u + el];
            float4 x3 = E4[(sb + i3) * 16u + el];
            f4_add(a, x0); f4_add(a, x1); f4_add(a, x2); f4_add(a, x3);
        }
        for (; e < end; e++) {
            unsigned src = g_csr[e];
            f4_add(a, E4[(sb + src) * 16u + el]);
        }
        float4 s = E4[(sb + n) * 16u + el];
        // epsilon passthrough (second model output) — covers all (s,n,col)
        ((float4*)out2)[(sb + n) * 16u + el] = s;
        float4 o;
        o.x = fmaf(sc, s.x, a.x); o.y = fmaf(sc, s.y, a.y);
        o.z = fmaf(sc, s.z, a.z); o.w = fmaf(sc, s.w, a.w);
        uint2 hi, lo;
        split4(o, hi, lo);
        *(uint2*)&Zh[(size_t)(sb + n) * DH + DIN + el * 4] = hi;
        *(uint2*)&Zl[(size_t)(sb + n) * DH + DIN + el * 4] = lo;
    }
}

// ---------------- layer-1 aggregation: one warp per (n, half), BOTH samples ----------------
// Indices loaded once serve two gathers (s=0, s=1): same MLP, half the loop overhead.
__global__ void k_agg1(const float* __restrict__ h,
                       unsigned short* __restrict__ Zh, unsigned short* __restrict__ Zl,
                       const float* __restrict__ epsv) {
    unsigned gw = (blockIdx.x * blockDim.x + threadIdx.x) >> 5;
    unsigned lane = threadIdx.x & 31;
    unsigned n = gw >> 1;
    unsigned half = gw & 1;
    if (n >= NN) return;
    const unsigned off = half * 32u + lane;       // float4 column within row
    const unsigned SOFF = (unsigned)NN * 64u;     // sample stride in float4s
    const float4* H = ((const float4*)h) + off;
    float sc = 1.0f + *epsv;

    float4 a0 = f4_zero(), a1 = f4_zero();
    int beg = g_rowptr[n], end = g_rowptr[n + 1];
    int e = beg;
    for (; e + 2 <= end; e += 2) {
        unsigned i0 = g_csr[e + 0], i1 = g_csr[e + 1];
        float4 p00 = H[i0 * 64u];
        float4 p01 = H[i0 * 64u + SOFF];
        float4 p10 = H[i1 * 64u];
        float4 p11 = H[i1 * 64u + SOFF];
        f4_add(a0, p00); f4_add(a0, p10);
        f4_add(a1, p01); f4_add(a1, p11);
    }
    if (e < end) {
        unsigned i0 = g_csr[e];
        f4_add(a0, H[i0 * 64u]);
        f4_add(a1, H[i0 * 64u + SOFF]);
    }
    float4 s0 = H[n * 64u];
    float4 s1 = H[n * 64u + SOFF];
    a0.x = fmaf(sc, s0.x, a0.x); a0.y = fmaf(sc, s0.y, a0.y);
    a0.z = fmaf(sc, s0.z, a0.z); a0.w = fmaf(sc, s0.w, a0.w);
    a1.x = fmaf(sc, s1.x, a1.x); a1.y = fmaf(sc, s1.y, a1.y);
    a1.z = fmaf(sc, s1.z, a1.z); a1.w = fmaf(sc, s1.w, a1.w);

    uint2 hi0, lo0, hi1, lo1;
    split4(a0, hi0, lo0);
    split4(a1, hi1, lo1);
    size_t col = half * 128 + lane * 4;
    size_t row0 = (size_t)n * DOUT + col;
    size_t row1 = (size_t)(NN + n) * DOUT + col;
    *(uint2*)&Zh[row0] = hi0;
    *(uint2*)&Zl[row0] = lo0;
    *(uint2*)&Zh[row1] = hi1;
    *(uint2*)&Zl[row1] = lo1;
}

// ---------------- bf16x3 MMA GEMM (BM128 x BN64): multi-stage cp.async + ldmatrix ----------------
// MODE 0: C = relu(acc + bias); MODE 1: C = acc; MODE 2: C = relu(acc + bias + yX[m%NN]).
// Dynamic smem: A region = STAGES*16384 B (2 planes x 8192), B region = STAGES*8192 B.
template <int K, int LD, int MODE, int STAGES>
__global__ void __launch_bounds__(256)
k_gemm3(const __nv_bfloat16* __restrict__ Ah, const __nv_bfloat16* __restrict__ Al,
        const __nv_bfloat16* __restrict__ Wh, const __nv_bfloat16* __restrict__ Wl,
        const float* __restrict__ bias, float* __restrict__ C,
        int M, const float* __restrict__ yX) {
    extern __shared__ __align__(16) unsigned char smem_raw[];
    const int T = K / 32;
    const uint32_t A_PLANE = 8192, A_ST = 16384;   // bytes per plane / per stage
    const uint32_t B_PLANE = 4096, B_ST = 8192;

    int tid = threadIdx.x, lane = tid & 31, wid = tid >> 5;
    int wm = wid & 3, wn = wid >> 2;
    int row0 = blockIdx.x * 128, col0 = blockIdx.y * 64;
    int g = lane >> 2, tg = lane & 3;

    uint32_t sA_u = (uint32_t)__cvta_generic_to_shared(smem_raw);
    uint32_t sB_u = sA_u + STAGES * A_ST;

    uint32_t aBase, bBase;
    {
        int q = lane >> 3;
        int ar = wm * 32 + (q & 1) * 8 + (lane & 7);
        int ach = ((q >> 1)) ^ ((ar >> 1) & 3);
        aBase = sA_u + (uint32_t)(ar * 64 + ach * 16);
        int br = wn * 32 + (q >> 1) * 8 + (lane & 7);
        int bch = ((q & 1)) ^ ((br >> 1) & 3);
        bBase = sB_u + (uint32_t)(br * 64 + bch * 16);
    }

    const __nv_bfloat16* Aplane[2] = {Ah, Al};
    const __nv_bfloat16* Wplane[2] = {Wh, Wl};

    float acc[2][4][4];
    #pragma unroll
    for (int mi = 0; mi < 2; mi++)
        #pragma unroll
        for (int ni = 0; ni < 4; ni++)
            #pragma unroll
            for (int j = 0; j < 4; j++) acc[mi][ni][j] = 0.f;

    auto load_tile = [&](int stage, int k0) {
        #pragma unroll
        for (int i = 0; i < 4; i++) {           // A: 128 rows x 4 chunks x 2 planes
            int idx = tid + i * 256;
            int p = idx >> 9, rem = idx & 511;
            int r = rem >> 2, c = rem & 3;
            int gr = row0 + r; if (gr >= M) gr = M - 1;
            const __nv_bfloat16* src = Aplane[p] + (size_t)gr * LD + k0 + c * 8;
            uint32_t dst = sA_u + stage * A_ST + p * A_PLANE
                         + (uint32_t)((r * 4 + (c ^ ((r >> 1) & 3))) * 16);
            cp16(dst, src);
        }
        #pragma unroll
        for (int i = 0; i < 2; i++) {           // B: 64 rows x 4 chunks x 2 planes
            int idx = tid + i * 256;
            int p = idx >> 8, rem = idx & 255;
            int r = rem >> 2, c = rem & 3;
            const __nv_bfloat16* src = Wplane[p] + (size_t)(col0 + r) * LD + k0 + c * 8;
            uint32_t dst = sB_u + stage * B_ST + p * B_PLANE
                         + (uint32_t)((r * 4 + (c ^ ((r >> 1) & 3))) * 16);
            cp16(dst, src);
        }
    };

    // prologue: fill STAGES-1 stages
    #pragma unroll
    for (int s = 0; s < STAGES - 1; s++) {
        if (s < T) load_tile(s, s * 32);
        cp_commit();
    }

    int wr_stage = (STAGES - 1) % STAGES;
    int rd_stage = 0;
    for (int t = 0; t < T; t++) {
        if (t + STAGES - 1 < T) load_tile(wr_stage, (t + STAGES - 1) * 32);
        cp_commit();                   // unconditional: keeps group count aligned
        cp_wait<STAGES - 1>();         // tile t's group is now complete
        __syncthreads();

        uint32_t aS = aBase + rd_stage * A_ST;
        uint32_t bS = bBase + rd_stage * B_ST;

        #pragma unroll
        for (int ks = 0; ks < 2; ks++) {
            uint32_t kx = ks ? 32u : 0u;
            uint32_t bh[8], bl[8], ah[2][4], al[2][4];
            ldsm_x4(bh[0], bh[1], bh[2], bh[3], bS ^ kx);
            ldsm_x4(bh[4], bh[5], bh[6], bh[7], (bS + 1024) ^ kx);
            ldsm_x4(bl[0], bl[1], bl[2], bl[3], (bS + B_PLANE) ^ kx);
            ldsm_x4(bl[4], bl[5], bl[6], bl[7], (bS + B_PLANE + 1024) ^ kx);
            ldsm_x4(ah[0][0], ah[0][1], ah[0][2], ah[0][3], aS ^ kx);
            ldsm_x4(ah[1][0], ah[1][1], ah[1][2], ah[1][3], (aS + 1024) ^ kx);
            ldsm_x4(al[0][0], al[0][1], al[0][2], al[0][3], (aS + A_PLANE) ^ kx);
            ldsm_x4(al[1][0], al[1][1], al[1][2], al[1][3], (aS + A_PLANE + 1024) ^ kx);
            #pragma unroll
            for (int mi = 0; mi < 2; mi++)
                #pragma unroll
                for (int ni = 0; ni < 4; ni++) {
                    mma_bf16(acc[mi][ni], ah[mi], &bh[ni * 2]);
                    mma_bf16(acc[mi][ni], al[mi], &bh[ni * 2]);
                    mma_bf16(acc[mi][ni], ah[mi], &bl[ni * 2]);
                }
        }
        __syncthreads();
        wr_stage = (wr_stage + 1 == STAGES) ? 0 : wr_stage + 1;
        rd_stage = (rd_stage + 1 == STAGES) ? 0 : rd_stage + 1;
    }

    #pragma unroll
    for (int mi = 0; mi < 2; mi++) {
        #pragma unroll
        for (int ni = 0; ni < 4; ni++) {
            int m = row0 + wm * 32 + mi * 16 + g;
            int n = col0 + wn * 32 + ni * 8 + 2 * tg;
            float bx = 0.f, by = 0.f;
            if (MODE != 1) { bx = bias[n]; by = bias[n + 1]; }
            #pragma unroll
            for (int half = 0; half < 2; half++) {
                int mm = m + half * 8;
                if (mm < M) {
                    float vx = acc[mi][ni][half * 2 + 0] + bx;
                    float vy = acc[mi][ni][half * 2 + 1] + by;
                    if (MODE == 2) {
                        int n0 = (mm >= NN) ? mm - NN : mm;
                        float2 yv = *(const float2*)&yX[(size_t)n0 * DOUT + n];
                        vx += yv.x; vy += yv.y;
                    }
                    float2 o;
                    if (MODE == 1) { o.x = vx; o.y = vy; }
                    else { o.x = fmaxf(vx, 0.f); o.y = fmaxf(vy, 0.f); }
                    *(float2*)&C[(size_t)mm * DOUT + n] = o;
                }
            }
        }
    }
}

// ---------------- launch ----------------
extern "C" void kernel_launch(void* const* d_in, const int* in_sizes, int n_in,
                              void* d_out, int out_size) {
    const float* X    = (const float*)d_in[0];
    const float* eps  = (const float*)d_in[1];
    const int*   esrc = (const int*)d_in[2];
    const int*   edst = (const int*)d_in[3];
    const float* W0   = (const float*)d_in[4];
    const float* b0   = (const float*)d_in[5];
    const float* W1   = (const float*)d_in[6];
    const float* b1   = (const float*)d_in[7];
    const float* e0   = (const float*)d_in[8];
    const float* e1   = (const float*)d_in[9];
    float* out = (float*)d_out;

    float *h1, *yX;
    unsigned short *A0h, *A0l, *A1h, *A1l, *W0h, *W0l, *W1h, *W1l;
    int* counts;
    cudaGetSymbolAddress((void**)&h1,  g_h1);
    cudaGetSymbolAddress((void**)&yX,  g_yX);
    cudaGetSymbolAddress((void**)&A0h, g_A0h);
    cudaGetSymbolAddress((void**)&A0l, g_A0l);
    cudaGetSymbolAddress((void**)&A1h, g_A1h);
    cudaGetSymbolAddress((void**)&A1l, g_A1l);
    cudaGetSymbolAddress((void**)&W0h, g_W0h);
    cudaGetSymbolAddress((void**)&W0l, g_W0l);
    cudaGetSymbolAddress((void**)&W1h, g_W1h);
    cudaGetSymbolAddress((void**)&W1l, g_W1l);
    cudaGetSymbolAddress((void**)&counts, g_counts);

    const int SM2 = 2 * (16384 + 8192);            // 49152 B (2-stage)
    const int SM3 = 3 * (16384 + 8192);            // 73728 B (3-stage)
    cudaFuncSetAttribute(k_gemm3<DIN, DH, 1, 2>,
                         cudaFuncAttributeMaxDynamicSharedMemorySize, SM2);
    cudaFuncSetAttribute(k_gemm3<DNOISE, DH, 2, 2>,
                         cudaFuncAttributeMaxDynamicSharedMemorySize, SM2);
    cudaFuncSetAttribute(k_gemm3<DOUT, DOUT, 0, 3>,
                         cudaFuncAttributeMaxDynamicSharedMemorySize, SM3);

    // CSR build
    cudaMemsetAsync(counts, 0, NN * sizeof(int));
    k_count<<<(EE + 255) / 256, 256>>>(edst);
    k_scan<<<1, 1024>>>();
    k_scatter<<<(EE + 255) / 256, 256>>>(esrc, edst);

    // layer 0 aggregation (fused concat + eps passthrough, 2 warps/node)
    k_agg0<<<(NN * 2 * 32 + 255) / 256, 256>>>(X, eps, A0h, A0l, e0,
                                               out + (size_t)SN * DOUT);

    // weight pre-split
    k_split_w<DH><<<(256 * DH + 255) / 256, 256>>>(W0, W0h, W0l);
    k_split_w<DOUT><<<(256 * DOUT + 255) / 256, 256>>>(W1, W1h, W1l);

    // layer 0 GEMM, algebraically split
    {
        dim3 grid((NN + 127) / 128, DOUT / 64);
        k_gemm3<DIN, DH, 1, 2><<<grid, 256, SM2>>>(
            (const __nv_bfloat16*)A0h, (const __nv_bfloat16*)A0l,
            (const __nv_bfloat16*)W0h, (const __nv_bfloat16*)W0l,
            b0, yX, NN, nullptr);
    }
    {
        dim3 grid((SN + 127) / 128, DOUT / 64);
        k_gemm3<DNOISE, DH, 2, 2><<<grid, 256, SM2>>>(
            (const __nv_bfloat16*)(A0h + DIN), (const __nv_bfloat16*)(A0l + DIN),
            (const __nv_bfloat16*)(W0h + DIN), (const __nv_bfloat16*)(W0l + DIN),
            b0, h1, SN, yX);
    }

    // layer 1: warp per (n, half) covering both samples
    k_agg1<<<(NN * 2 * 32 + 255) / 256, 256>>>(h1, A1h, A1l, e1);
    {
        dim3 grid((SN + 127) / 128, DOUT / 64);
        k_gemm3<DOUT, DOUT, 0, 3><<<grid, 256, SM3>>>(
            (const __nv_bfloat16*)A1h, (const __nv_bfloat16*)A1l,
            (const __nv_bfloat16*)W1h, (const __nv_bfloat16*)W1l,
            b1, out, SN, nullptr);  // relu == outer relu too
    }
}

// round 14
// speedup vs baseline: 1.1137x; 1.1137x over previous
#include <cuda_runtime.h>
#include <cuda_bf16.h>
#include <cstdint>

#define NN 50000
#define EE 800000
#define SS 2
#define DIN 128
#define DNOISE 64
#define DH 192          // DIN + DNOISE
#define DOUT 256
#define SN (SS * NN)    // 100000 rows

// ---------------- scratch (static device globals; no allocation) ----------------
__device__ float          g_h1[(size_t)SN * DOUT];        // gemmE output (fp32)
__device__ float          g_yX[(size_t)NN * DOUT];        // zX @ W0X (sample-invariant)
__device__ unsigned short g_A0h[(size_t)SN * DH];         // layer-0 A, bf16 hi plane
__device__ unsigned short g_A0l[(size_t)SN * DH];
__device__ unsigned short g_A1h[(size_t)SN * DOUT];
__device__ unsigned short g_A1l[(size_t)SN * DOUT];
__device__ unsigned short g_W0h[DOUT * DH];               // W0^T split planes [n][k]
__device__ unsigned short g_W0l[DOUT * DH];
__device__ unsigned short g_W1h[DOUT * DOUT];
__device__ unsigned short g_W1l[DOUT * DOUT];
__device__ int g_counts[NN];
__device__ int g_rowptr[NN + 1];
__device__ int g_cursor[NN];
__device__ int g_csr[EE];

// ---------------- small helpers ----------------
__device__ __forceinline__ float4 f4_zero() { return make_float4(0.f, 0.f, 0.f, 0.f); }
__device__ __forceinline__ void f4_add(float4& a, const float4 b) {
    a.x += b.x; a.y += b.y; a.z += b.z; a.w += b.w;
}

__device__ __forceinline__ void mma_bf16(float* c, const uint32_t* a, const uint32_t* b) {
    asm volatile(
        "mma.sync.aligned.m16n8k16.row.col.f32.bf16.bf16.f32 "
        "{%0,%1,%2,%3},{%4,%5,%6,%7},{%8,%9},{%0,%1,%2,%3};\n"
        : "+f"(c[0]), "+f"(c[1]), "+f"(c[2]), "+f"(c[3])
        : "r"(a[0]), "r"(a[1]), "r"(a[2]), "r"(a[3]), "r"(b[0]), "r"(b[1]));
}

__device__ __forceinline__ void ldsm_x4(uint32_t& r0, uint32_t& r1, uint32_t& r2, uint32_t& r3,
                                        uint32_t addr) {
    asm volatile("ldmatrix.sync.aligned.m8n8.x4.shared.b16 {%0,%1,%2,%3},[%4];"
                 : "=r"(r0), "=r"(r1), "=r"(r2), "=r"(r3) : "r"(addr));
}

__device__ __forceinline__ void cp16(uint32_t smem_dst, const void* gsrc) {
    asm volatile("cp.async.ca.shared.global [%0], [%1], 16;\n" :: "r"(smem_dst), "l"(gsrc));
}
__device__ __forceinline__ void cp_commit() { asm volatile("cp.async.commit_group;\n"); }
template <int N>
__device__ __forceinline__ void cp_wait() { asm volatile("cp.async.wait_group %0;\n" :: "n"(N)); }

// split one float into bf16 hi + bf16 lo (bits)
__device__ __forceinline__ void splitf(float x, unsigned short& h, unsigned short& l) {
    __nv_bfloat16 hb = __float2bfloat16(x);
    __nv_bfloat16 lb = __float2bfloat16(x - __bfloat162float(hb));
    h = __bfloat16_as_ushort(hb);
    l = __bfloat16_as_ushort(lb);
}
__device__ __forceinline__ void split4(float4 v, uint2& hi, uint2& lo) {
    unsigned short hx, lx, hy, ly, hz, lz, hw, lw;
    splitf(v.x, hx, lx); splitf(v.y, hy, ly);
    splitf(v.z, hz, lz); splitf(v.w, hw, lw);
    hi.x = (uint32_t)hx | ((uint32_t)hy << 16);
    hi.y = (uint32_t)hz | ((uint32_t)hw << 16);
    lo.x = (uint32_t)lx | ((uint32_t)ly << 16);
    lo.y = (uint32_t)lz | ((uint32_t)lw << 16);
}

// ---------------- CSR build ----------------
__global__ void k_count(const int* __restrict__ dst) {
    int e = blockIdx.x * blockDim.x + threadIdx.x;
    if (e < EE) atomicAdd(&g_counts[dst[e]], 1);
}

__global__ void k_scan() {
    const int CH = (NN + 1023) / 1024;   // 49
    __shared__ int wsum[32];
    int t = threadIdx.x, lane = t & 31, w = t >> 5;
    int base = t * CH;
    int sum = 0;
    for (int i = 0; i < CH; i++) {
        int n = base + i;
        if (n < NN) sum += g_counts[n];
    }
    int incl = sum;
    #pragma unroll
    for (int d = 1; d < 32; d <<= 1) {
        int y = __shfl_up_sync(0xffffffffu, incl, d);
        if (lane >= d) incl += y;
    }
    if (lane == 31) wsum[w] = incl;
    __syncthreads();
    if (w == 0) {
        int v = wsum[lane];
        #pragma unroll
        for (int d = 1; d < 32; d <<= 1) {
            int y = __shfl_up_sync(0xffffffffu, v, d);
            if (lane >= d) v += y;
        }
        wsum[lane] = v;
    }
    __syncthreads();
    int offset = incl - sum + (w > 0 ? wsum[w - 1] : 0);
    int run = offset;
    for (int i = 0; i < CH; i++) {
        int n = base + i;
        if (n < NN) {
            g_rowptr[n] = run;
            g_cursor[n] = run;
            run += g_counts[n];
        }
    }
    if (t == 1023) g_rowptr[NN] = wsum[31];
}

__global__ void k_scatter(const int* __restrict__ src, const int* __restrict__ dst) {
    int e = blockIdx.x * blockDim.x + threadIdx.x;
    if (e < EE) {
        int p = atomicAdd(&g_cursor[dst[e]], 1);
        g_csr[p] = src[e];
    }
}

// ---------------- weight pre-split: W[K][256] fp32 -> Wt planes [256][K] bf16 ----------------
template <int K>
__global__ void k_split_w(const float* __restrict__ W,
                          unsigned short* __restrict__ Wh, unsigned short* __restrict__ Wl) {
    int id = blockIdx.x * blockDim.x + threadIdx.x;
    if (id >= 256 * K) return;
    int n = id % 256, k = id / 256;
    unsigned short h, l;
    splitf(W[(size_t)k * 256 + n], h, l);
    Wh[(size_t)n * K + k] = h;
    Wl[(size_t)n * K + k] = l;
}

// ---------------- layer-0 aggregation (fused concat + eps passthrough) ----------------
// TWO warps per node: role 0 = X part; role 1 = eps parts (both samples) + out2 store.
__global__ void k_agg0(const float* __restrict__ X, const float* __restrict__ eps,
                       unsigned short* __restrict__ Zh, unsigned short* __restrict__ Zl,
                       const float* __restrict__ epsv, float* __restrict__ out2) {
    unsigned gw = (blockIdx.x * blockDim.x + threadIdx.x) >> 5;
    unsigned lane = threadIdx.x & 31;
    unsigned n = gw >> 1;
    unsigned role = gw & 1;
    if (n >= NN) return;
    float sc = 1.0f + *epsv;
    int beg = g_rowptr[n], end = g_rowptr[n + 1];

    if (role == 0) {
        const float4* X4 = (const float4*)X;     // [NN][32]
        float4 a = f4_zero();
        int e = beg;
        for (; e + 4 <= end; e += 4) {
            unsigned i0 = g_csr[e + 0], i1 = g_csr[e + 1];
            unsigned i2 = g_csr[e + 2], i3 = g_csr[e + 3];
            float4 x0 = X4[i0 * 32u + lane];
            float4 x1 = X4[i1 * 32u + lane];
            float4 x2 = X4[i2 * 32u + lane];
            float4 x3 = X4[i3 * 32u + lane];
            f4_add(a, x0); f4_add(a, x1); f4_add(a, x2); f4_add(a, x3);
        }
        for (; e < end; e++) {
            unsigned src = g_csr[e];
            f4_add(a, X4[src * 32u + lane]);
        }
        float4 s = X4[n * 32u + lane];
        float4 o;
        o.x = fmaf(sc, s.x, a.x); o.y = fmaf(sc, s.y, a.y);
        o.z = fmaf(sc, s.z, a.z); o.w = fmaf(sc, s.w, a.w);
        uint2 hi, lo;
        split4(o, hi, lo);
        *(uint2*)&Zh[(size_t)n * DH + lane * 4] = hi;
        *(uint2*)&Zl[(size_t)n * DH + lane * 4] = lo;
    } else {
        const float4* E4 = (const float4*)eps;   // [2*NN][16]
        unsigned sb = (lane >> 4) * NN;          // sample base
        unsigned el = lane & 15;
        float4 a = f4_zero();
        int e = beg;
        for (; e + 4 <= end; e += 4) {
            unsigned i0 = g_csr[e + 0], i1 = g_csr[e + 1];
            unsigned i2 = g_csr[e + 2], i3 = g_csr[e + 3];
            float4 x0 = E4[(sb + i0) * 16u + el];
            float4 x1 = E4[(sb + i1) * 16u + el];
            float4 x2 = E4[(sb + i2) * 16u + el];
            float4 x3 = E4[(sb + i3) * 16u + el];
            f4_add(a, x0); f4_add(a, x1); f4_add(a, x2); f4_add(a, x3);
        }
        for (; e < end; e++) {
            unsigned src = g_csr[e];
            f4_add(a, E4[(sb + src) * 16u + el]);
        }
        float4 s = E4[(sb + n) * 16u + el];
        // epsilon passthrough (second model output) — covers all (s,n,col)
        ((float4*)out2)[(sb + n) * 16u + el] = s;
        float4 o;
        o.x = fmaf(sc, s.x, a.x); o.y = fmaf(sc, s.y, a.y);
        o.z = fmaf(sc, s.z, a.z); o.w = fmaf(sc, s.w, a.w);
        uint2 hi, lo;
        split4(o, hi, lo);
        *(uint2*)&Zh[(size_t)(sb + n) * DH + DIN + el * 4] = hi;
        *(uint2*)&Zl[(size_t)(sb + n) * DH + DIN + el * 4] = lo;
    }
}

// ---------------- layer-1 aggregation: TWO warps per (s,n), one 128-col half each ----------------
__global__ void k_agg1(const float* __restrict__ h,
                       unsigned short* __restrict__ Zh, unsigned short* __restrict__ Zl,
                       const float* __restrict__ epsv) {
    unsigned gw = (blockIdx.x * blockDim.x + threadIdx.x) >> 5;
    unsigned lane = threadIdx.x & 31;
    unsigned sn = gw >> 1;          // (s*NN + n)
    unsigned half = gw & 1;
    if (sn >= SN) return;
    unsigned n = sn % NN;
    unsigned s = sn / NN;
    const float4* hs = ((const float4*)h) + (size_t)s * NN * 64 + half * 32 + lane;
    float sc = 1.0f + *epsv;

    float4 a = f4_zero();
    int beg = g_rowptr[n], end = g_rowptr[n + 1];
    int e = beg;
    for (; e + 4 <= end; e += 4) {
        unsigned i0 = g_csr[e + 0], i1 = g_csr[e + 1];
        unsigned i2 = g_csr[e + 2], i3 = g_csr[e + 3];
        float4 p0 = hs[i0 * 64u];
        float4 p1 = hs[i1 * 64u];
        float4 p2 = hs[i2 * 64u];
        float4 p3 = hs[i3 * 64u];
        f4_add(a, p0); f4_add(a, p1); f4_add(a, p2); f4_add(a, p3);
    }
    for (; e < end; e++) {
        unsigned src = g_csr[e];
        f4_add(a, hs[src * 64u]);
    }
    float4 sv = hs[n * 64u];
    a.x = fmaf(sc, sv.x, a.x); a.y = fmaf(sc, sv.y, a.y);
    a.z = fmaf(sc, sv.z, a.z); a.w = fmaf(sc, sv.w, a.w);

    uint2 hi, lo;
    split4(a, hi, lo);
    size_t row = (size_t)sn * DOUT + half * 128;
    *(uint2*)&Zh[row + lane * 4] = hi;
    *(uint2*)&Zl[row + lane * 4] = lo;
}

// ---------------- bf16x3 MMA GEMM (BM128 x BN64): static smem 2-stage + ldmatrix ----------------
// MODE 0: C = relu(acc + bias); MODE 1: C = acc; MODE 2: C = relu(acc + bias + yX[m%NN]).
template <int K, int LD, int MODE>
__global__ void __launch_bounds__(256)
k_gemm3(const __nv_bfloat16* __restrict__ Ah, const __nv_bfloat16* __restrict__ Al,
        const __nv_bfloat16* __restrict__ Wh, const __nv_bfloat16* __restrict__ Wl,
        const float* __restrict__ bias, float* __restrict__ C,
        int M, const float* __restrict__ yX) {
    __shared__ alignas(16) __nv_bfloat16 sA[2][2][128 * 32];  // [stage][plane]
    __shared__ alignas(16) __nv_bfloat16 sB[2][2][64 * 32];

    const int T = K / 32;
    const uint32_t A_PLANE = 128 * 32 * 2, A_STAGE = 2 * A_PLANE;   // bytes
    const uint32_t B_PLANE = 64 * 32 * 2,  B_STAGE = 2 * B_PLANE;

    int tid = threadIdx.x, lane = tid & 31, wid = tid >> 5;
    int wm = wid & 3, wn = wid >> 2;
    int row0 = blockIdx.x * 128, col0 = blockIdx.y * 64;
    int g = lane >> 2, tg = lane & 3;

    uint32_t sA_u = (uint32_t)__cvta_generic_to_shared(&sA[0][0][0]);
    uint32_t sB_u = (uint32_t)__cvta_generic_to_shared(&sB[0][0][0]);

    uint32_t aBase, bBase;
    {
        int q = lane >> 3;
        int ar = wm * 32 + (q & 1) * 8 + (lane & 7);
        int ae = (q >> 1) * 8;
        int ach = (ae >> 3) ^ ((ar >> 1) & 3);
        aBase = sA_u + (uint32_t)(ar * 64 + ach * 16);
        int br = wn * 32 + (q >> 1) * 8 + (lane & 7);
        int be = (q & 1) * 8;
        int bch = (be >> 3) ^ ((br >> 1) & 3);
        bBase = sB_u + (uint32_t)(br * 64 + bch * 16);
    }

    const __nv_bfloat16* Aplane[2] = {Ah, Al};
    const __nv_bfloat16* Wplane[2] = {Wh, Wl};

    float acc[2][4][4];
    #pragma unroll
    for (int mi = 0; mi < 2; mi++)
        #pragma unroll
        for (int ni = 0; ni < 4; ni++)
            #pragma unroll
            for (int j = 0; j < 4; j++) acc[mi][ni][j] = 0.f;

    auto load_tile = [&](int stage, int k0) {
        #pragma unroll
        for (int i = 0; i < 4; i++) {           // A: 128 rows x 4 chunks x 2 planes
            int idx = tid + i * 256;
            int p = idx >> 9, rem = idx & 511;
            int r = rem >> 2, c = rem & 3;
            int gr = row0 + r; if (gr >= M) gr = M - 1;
            const __nv_bfloat16* src = Aplane[p] + (size_t)gr * LD + k0 + c * 8;
            uint32_t dst = sA_u + stage * A_STAGE + p * A_PLANE
                         + (uint32_t)((r * 4 + (c ^ ((r >> 1) & 3))) * 16);
            cp16(dst, src);
        }
        #pragma unroll
        for (int i = 0; i < 2; i++) {           // B: 64 rows x 4 chunks x 2 planes
            int idx = tid + i * 256;
            int p = idx >> 8, rem = idx & 255;
            int r = rem >> 2, c = rem & 3;
            const __nv_bfloat16* src = Wplane[p] + (size_t)(col0 + r) * LD + k0 + c * 8;
            uint32_t dst = sB_u + stage * B_STAGE + p * B_PLANE
                         + (uint32_t)((r * 4 + (c ^ ((r >> 1) & 3))) * 16);
            cp16(dst, src);
        }
    };

    load_tile(0, 0);
    cp_commit();

    for (int t = 0; t < T; t++) {
        if (t + 1 < T) {
            load_tile((t + 1) & 1, (t + 1) * 32);
            cp_commit();
            cp_wait<1>();
        } else {
            cp_wait<0>();
        }
        __syncthreads();

        uint32_t aS = aBase + (t & 1) * A_STAGE;
        uint32_t bS = bBase + (t & 1) * B_STAGE;

        #pragma unroll
        for (int ks = 0; ks < 2; ks++) {
            uint32_t kx = ks ? 32u : 0u;
            uint32_t bh[8], bl[8], ah[2][4], al[2][4];
            ldsm_x4(bh[0], bh[1], bh[2], bh[3], bS ^ kx);
            ldsm_x4(bh[4], bh[5], bh[6], bh[7], (bS + 1024) ^ kx);
            ldsm_x4(bl[0], bl[1], bl[2], bl[3], (bS + B_PLANE) ^ kx);
            ldsm_x4(bl[4], bl[5], bl[6], bl[7], (bS + B_PLANE + 1024) ^ kx);
            ldsm_x4(ah[0][0], ah[0][1], ah[0][2], ah[0][3], aS ^ kx);
            ldsm_x4(ah[1][0], ah[1][1], ah[1][2], ah[1][3], (aS + 1024) ^ kx);
            ldsm_x4(al[0][0], al[0][1], al[0][2], al[0][3], (aS + A_PLANE) ^ kx);
            ldsm_x4(al[1][0], al[1][1], al[1][2], al[1][3], (aS + A_PLANE + 1024) ^ kx);
            #pragma unroll
            for (int mi = 0; mi < 2; mi++)
                #pragma unroll
                for (int ni = 0; ni < 4; ni++) {
                    mma_bf16(acc[mi][ni], ah[mi], &bh[ni * 2]);
                    mma_bf16(acc[mi][ni], al[mi], &bh[ni * 2]);
                    mma_bf16(acc[mi][ni], ah[mi], &bl[ni * 2]);
                }
        }
        __syncthreads();
    }

    #pragma unroll
    for (int mi = 0; mi < 2; mi++) {
        #pragma unroll
        for (int ni = 0; ni < 4; ni++) {
            int m = row0 + wm * 32 + mi * 16 + g;
            int n = col0 + wn * 32 + ni * 8 + 2 * tg;
            float bx = 0.f, by = 0.f;
            if (MODE != 1) { bx = bias[n]; by = bias[n + 1]; }
            #pragma unroll
            for (int half = 0; half < 2; half++) {
                int mm = m + half * 8;
                if (mm < M) {
                    float vx = acc[mi][ni][half * 2 + 0] + bx;
                    float vy = acc[mi][ni][half * 2 + 1] + by;
                    if (MODE == 2) {
                        int n0 = (mm >= NN) ? mm - NN : mm;
                        float2 yv = *(const float2*)&yX[(size_t)n0 * DOUT + n];
                        vx += yv.x; vy += yv.y;
                    }
                    float2 o;
                    if (MODE == 1) { o.x = vx; o.y = vy; }
                    else { o.x = fmaxf(vx, 0.f); o.y = fmaxf(vy, 0.f); }
                    *(float2*)&C[(size_t)mm * DOUT + n] = o;
                }
            }
        }
    }
}

// ---------------- launch ----------------
extern "C" void kernel_launch(void* const* d_in, const int* in_sizes, int n_in,
                              void* d_out, int out_size) {
    const float* X    = (const float*)d_in[0];
    const float* eps  = (const float*)d_in[1];
    const int*   esrc = (const int*)d_in[2];
    const int*   edst = (const int*)d_in[3];
    const float* W0   = (const float*)d_in[4];
    const float* b0   = (const float*)d_in[5];
    const float* W1   = (const float*)d_in[6];
    const float* b1   = (const float*)d_in[7];
    const float* e0   = (const float*)d_in[8];
    const float* e1   = (const float*)d_in[9];
    float* out = (float*)d_out;

    float *h1, *yX;
    unsigned short *A0h, *A0l, *A1h, *A1l, *W0h, *W0l, *W1h, *W1l;
    int* counts;
    cudaGetSymbolAddress((void**)&h1,  g_h1);
    cudaGetSymbolAddress((void**)&yX,  g_yX);
    cudaGetSymbolAddress((void**)&A0h, g_A0h);
    cudaGetSymbolAddress((void**)&A0l, g_A0l);
    cudaGetSymbolAddress((void**)&A1h, g_A1h);
    cudaGetSymbolAddress((void**)&A1l, g_A1l);
    cudaGetSymbolAddress((void**)&W0h, g_W0h);
    cudaGetSymbolAddress((void**)&W0l, g_W0l);
    cudaGetSymbolAddress((void**)&W1h, g_W1h);
    cudaGetSymbolAddress((void**)&W1l, g_W1l);
    cudaGetSymbolAddress((void**)&counts, g_counts);

    // CSR build
    cudaMemsetAsync(counts, 0, NN * sizeof(int));
    k_count<<<(EE + 255) / 256, 256>>>(edst);
    k_scan<<<1, 1024>>>();
    k_scatter<<<(EE + 255) / 256, 256>>>(esrc, edst);

    // layer 0 aggregation (fused concat + eps passthrough, 2 warps/node)
    k_agg0<<<(NN * 2 * 32 + 255) / 256, 256>>>(X, eps, A0h, A0l, e0,
                                               out + (size_t)SN * DOUT);

    // weight pre-split
    k_split_w<DH><<<(256 * DH + 255) / 256, 256>>>(W0, W0h, W0l);
    k_split_w<DOUT><<<(256 * DOUT + 255) / 256, 256>>>(W1, W1h, W1l);

    // layer 0 GEMM, algebraically split
    {
        dim3 grid((NN + 127) / 128, DOUT / 64);
        k_gemm3<DIN, DH, 1><<<grid, 256>>>(
            (const __nv_bfloat16*)A0h, (const __nv_bfloat16*)A0l,
            (const __nv_bfloat16*)W0h, (const __nv_bfloat16*)W0l,
            b0, yX, NN, nullptr);
    }
    {
        dim3 grid((SN + 127) / 128, DOUT / 64);
        k_gemm3<DNOISE, DH, 2><<<grid, 256>>>(
            (const __nv_bfloat16*)(A0h + DIN), (const __nv_bfloat16*)(A0l + DIN),
            (const __nv_bfloat16*)(W0h + DIN), (const __nv_bfloat16*)(W0l + DIN),
            b0, h1, SN, yX);
    }

    // layer 1 (2 warps per (s,n))
    k_agg1<<<(SN * 2 * 32 + 255) / 256, 256>>>(h1, A1h, A1l, e1);
    {
        dim3 grid((SN + 127) / 128, DOUT / 64);
        k_gemm3<DOUT, DOUT, 0><<<grid, 256>>>(
            (const __nv_bfloat16*)A1h, (const __nv_bfloat16*)A1l,
            (const __nv_bfloat16*)W1h, (const __nv_bfloat16*)W1l,
            b1, out, SN, nullptr);  // relu == outer relu too
    }
}